// round 4
// baseline (speedup 1.0000x reference)
#include <cuda_runtime.h>
#include <math.h>
#include <stdint.h>

// Problem constants
#define B_      8
#define SEQ_    16384
#define D_      384
#define QKVD_   1152
#define H_      8
#define C_      48
#define TOK_    (B_ * SEQ_)          // 131072

// ---------------- scratch (static device globals; no allocs allowed) ----------------
__device__ float g_qkv[(size_t)TOK_ * QKVD_];      // 604 MB : x @ W_qkv
__device__ float g_attn[(size_t)TOK_ * D_];        // 201 MB : per-head attention output
__device__ float g_ctx[B_ * H_ * C_ * C_];         // unnormalized k^T v context
__device__ float g_sum[B_ * H_ * C_];              // sum of exp(k) over tokens
__device__ float g_Wtq[QKVD_ * D_];                // W_qkv transposed: [1152][384]
__device__ float g_Wtp[D_ * D_];                   // W_proj transposed: [384][384]

// ---------------- zero the atomic accumulators (graph replays!) ----------------
__global__ void zero_ctx_kernel() {
    int i = blockIdx.x * 256 + threadIdx.x;
    if (i < B_ * H_ * C_ * C_) g_ctx[i] = 0.0f;
    if (i < B_ * H_ * C_)      g_sum[i] = 0.0f;
}

// ---------------- weight transpose: src[R][Ccols] -> dst[Ccols][R] ----------------
__global__ void transpose_kernel(const float* __restrict__ src, float* __restrict__ dst,
                                 int R, int Ccols) {
    __shared__ float t[32][33];
    int bx = blockIdx.x * 32, by = blockIdx.y * 32;
    int tx = threadIdx.x, ty = threadIdx.y;
#pragma unroll
    for (int j = 0; j < 32; j += 8)
        t[ty + j][tx] = src[(size_t)(by + ty + j) * Ccols + bx + tx];
    __syncthreads();
#pragma unroll
    for (int j = 0; j < 32; j += 8)
        dst[(size_t)(bx + ty + j) * R + by + tx] = t[tx][ty + j];
}

// ================= tf32 mma.sync GEMM v2 =================
// C[M,N] = A[M,K] @ Bt[N,K]^T (+bias).  A row-major, Bt row-major (K contiguous).
// Block tile 128x128, BK=32, 8 warps (2x4), warp tile 64x32.
// m16n8k8 tf32 HMMA; cp.async double-buffered smem; pad-36 rows -> conflict-free LDS.

#define BM_ 128
#define BN_ 128
#define BK_ 32
#define PADS_ 36                    // floats per smem row

__device__ __forceinline__ uint32_t smem_u32(const void* p) {
    uint32_t a;
    asm("{ .reg .u64 t; cvta.to.shared.u64 t, %1; cvt.u32.u64 %0, t; }" : "=r"(a) : "l"(p));
    return a;
}
__device__ __forceinline__ void cp_async16(uint32_t dst, const void* src) {
    asm volatile("cp.async.cg.shared.global [%0], [%1], 16;" :: "r"(dst), "l"(src));
}
__device__ __forceinline__ uint32_t f2tf32u(float x) {
    uint32_t y;
    asm("cvt.rna.tf32.f32 %0, %1;" : "=r"(y) : "f"(x));
    return y;
}
__device__ __forceinline__ void mma_tf32(float* c, const uint32_t* a, const uint32_t* b) {
    asm volatile(
        "mma.sync.aligned.m16n8k8.row.col.f32.tf32.tf32.f32 "
        "{%0,%1,%2,%3}, {%4,%5,%6,%7}, {%8,%9}, {%0,%1,%2,%3};"
        : "+f"(c[0]), "+f"(c[1]), "+f"(c[2]), "+f"(c[3])
        : "r"(a[0]), "r"(a[1]), "r"(a[2]), "r"(a[3]), "r"(b[0]), "r"(b[1]));
}

__global__ void __launch_bounds__(256, 2)
gemm_mma(const float* __restrict__ A, const float* __restrict__ Bt,
         const float* __restrict__ bias, float* __restrict__ Cm,
         int M, int N, int K, int has_bias)
{
    extern __shared__ float smem[];
    float* As = smem;                          // 2 * 128 * 36
    float* Bs = smem + 2 * BM_ * PADS_;        // 2 * 128 * 36

    const int tid = threadIdx.x;
    const int wid = tid >> 5;
    const int lane = tid & 31;
    const int m0 = blockIdx.y * BM_;
    const int n0 = blockIdx.x * BN_;
    const int wm = (wid & 1) * 64;       // 2 warps over M
    const int wn = (wid >> 1) * 32;      // 4 warps over N

    const int lr = lane >> 2;   // 0..7
    const int lc = lane & 3;    // 0..3

    // cp.async mapping: 128 rows x 8 float4/row; 256 threads -> 4 float4 each
    const int gr = tid >> 3;          // 0..31
    const int gc = (tid & 7) * 4;     // float offset

    const uint32_t as_base = smem_u32(As);
    const uint32_t bs_base = smem_u32(Bs);

    float acc[4][4][4];
#pragma unroll
    for (int i = 0; i < 4; i++)
#pragma unroll
        for (int j = 0; j < 4; j++)
#pragma unroll
            for (int r = 0; r < 4; r++) acc[i][j][r] = 0.0f;

    const int nch = K / BK_;

    // ---- load chunk 0 ----
    {
#pragma unroll
        for (int i = 0; i < 4; i++) {
            int row = gr + i * 32;
            cp_async16(as_base + (row * PADS_ + gc) * 4, &A[(size_t)(m0 + row) * K + gc]);
            cp_async16(bs_base + (row * PADS_ + gc) * 4, &Bt[(size_t)(n0 + row) * K + gc]);
        }
        asm volatile("cp.async.commit_group;");
    }

    for (int c = 0; c < nch; c++) {
        asm volatile("cp.async.wait_group 0;");
        __syncthreads();

        if (c + 1 < nch) {
            const int k0 = (c + 1) * BK_;
            const int buf = (c + 1) & 1;
            const uint32_t ab = as_base + buf * BM_ * PADS_ * 4;
            const uint32_t bb = bs_base + buf * BN_ * PADS_ * 4;
#pragma unroll
            for (int i = 0; i < 4; i++) {
                int row = gr + i * 32;
                cp_async16(ab + (row * PADS_ + gc) * 4, &A[(size_t)(m0 + row) * K + k0 + gc]);
                cp_async16(bb + (row * PADS_ + gc) * 4, &Bt[(size_t)(n0 + row) * K + k0 + gc]);
            }
            asm volatile("cp.async.commit_group;");
        }

        const float* as = As + (c & 1) * BM_ * PADS_;
        const float* bs = Bs + (c & 1) * BN_ * PADS_;

#pragma unroll
        for (int ks = 0; ks < 4; ks++) {
            const int kk = ks * 8 + lc;
            uint32_t afr[4][4];
#pragma unroll
            for (int mi = 0; mi < 4; mi++) {
                int r = wm + mi * 16 + lr;
                afr[mi][0] = f2tf32u(as[r * PADS_ + kk]);
                afr[mi][1] = f2tf32u(as[(r + 8) * PADS_ + kk]);
                afr[mi][2] = f2tf32u(as[r * PADS_ + kk + 4]);
                afr[mi][3] = f2tf32u(as[(r + 8) * PADS_ + kk + 4]);
            }
            uint32_t bfr[4][2];
#pragma unroll
            for (int nj = 0; nj < 4; nj++) {
                int nn = wn + nj * 8 + lr;
                bfr[nj][0] = f2tf32u(bs[nn * PADS_ + kk]);
                bfr[nj][1] = f2tf32u(bs[nn * PADS_ + kk + 4]);
            }
#pragma unroll
            for (int mi = 0; mi < 4; mi++)
#pragma unroll
                for (int nj = 0; nj < 4; nj++)
                    mma_tf32(acc[mi][nj], afr[mi], bfr[nj]);
        }
        __syncthreads();
    }

    // ---- epilogue ----
#pragma unroll
    for (int mi = 0; mi < 4; mi++) {
        const int r0 = m0 + wm + mi * 16 + lr;
#pragma unroll
        for (int nj = 0; nj < 4; nj++) {
            const int col = n0 + wn + nj * 8 + lc * 2;
            float2 b2 = make_float2(0.f, 0.f);
            if (has_bias) b2 = *(const float2*)&bias[col];
            float2 v0 = make_float2(acc[mi][nj][0] + b2.x, acc[mi][nj][1] + b2.y);
            float2 v1 = make_float2(acc[mi][nj][2] + b2.x, acc[mi][nj][3] + b2.y);
            *(float2*)&Cm[(size_t)r0 * N + col] = v0;
            *(float2*)&Cm[(size_t)(r0 + 8) * N + col] = v1;
        }
    }
}

// ---------------- context: ctx[b,h,c,d] += sum_n exp(k[n,c]) * v[n,d]; sum[c] += sum_n exp(k[n,c]) ----------------
#define NSPLIT_ 128
#define CROWS_  (SEQ_ / NSPLIT_)   // 128

__global__ void __launch_bounds__(288)
ctx_kernel()
{
    const int c = threadIdx.x;                 // 0..47
    const int g = threadIdx.y;                 // 0..5
    const int tid = g * 48 + c;                // 0..287
    const int split = blockIdx.x;
    const int h = blockIdx.y;
    const int b = blockIdx.z;
    const int n0 = split * CROWS_;
    const float* base = g_qkv + (size_t)(b * SEQ_ + n0) * QKVD_ + h * C_;

    __shared__ float ek[32][48];
    __shared__ float vs[32][48];

    float4 acc0 = make_float4(0.f, 0.f, 0.f, 0.f);
    float4 acc1 = make_float4(0.f, 0.f, 0.f, 0.f);
    float ssum = 0.0f;
    const int d0 = g * 8;

    for (int r0 = 0; r0 < CROWS_; r0 += 32) {
        __syncthreads();
        for (int idx = tid; idx < 32 * 48; idx += 288) {
            int r = idx / 48, cc = idx % 48;
            const float* rowp = base + (size_t)(r0 + r) * QKVD_ + cc;
            ek[r][cc] = __expf(rowp[384]);   // k block at cols 384..767
            vs[r][cc] = rowp[768];           // v block at cols 768..1151
        }
        __syncthreads();
#pragma unroll 4
        for (int r = 0; r < 32; r++) {
            float e = ek[r][c];
            if (g == 0) ssum += e;
            float4 v0 = *(const float4*)&vs[r][d0];
            float4 v1 = *(const float4*)&vs[r][d0 + 4];
            acc0.x += e * v0.x; acc0.y += e * v0.y; acc0.z += e * v0.z; acc0.w += e * v0.w;
            acc1.x += e * v1.x; acc1.y += e * v1.y; acc1.z += e * v1.z; acc1.w += e * v1.w;
        }
    }

    float* cp = g_ctx + (((size_t)(b * H_ + h)) * C_ + c) * C_ + d0;
    atomicAdd(&cp[0], acc0.x); atomicAdd(&cp[1], acc0.y);
    atomicAdd(&cp[2], acc0.z); atomicAdd(&cp[3], acc0.w);
    atomicAdd(&cp[4], acc1.x); atomicAdd(&cp[5], acc1.y);
    atomicAdd(&cp[6], acc1.z); atomicAdd(&cp[7], acc1.w);
    if (g == 0) atomicAdd(&g_sum[(b * H_ + h) * C_ + c], ssum);
}

// ---------------- attn: out[t, h*48+d] = softmax_c(q[t,h,:]) @ ctxn ----------------
#define TB_ 128

__global__ void __launch_bounds__(192)
attn_kernel()
{
    const int tb = blockIdx.x;
    const int h  = blockIdx.y;
    const int b  = blockIdx.z;
    const int tid = threadIdx.x;

    __shared__ float ctxn[48][48];
    __shared__ float eq[16][48];
    __shared__ float srow[16];
    __shared__ float sinv[48];

    if (tid < 48) sinv[tid] = 1.0f / g_sum[(b * H_ + h) * C_ + tid];
    __syncthreads();
    for (int idx = tid; idx < 48 * 48; idx += 192) {
        int c = idx / 48, d = idx % 48;
        ctxn[c][d] = g_ctx[(((size_t)(b * H_ + h)) * C_ + c) * C_ + d] * sinv[c];
    }

    const int n0 = tb * TB_;
    const float* qbase = g_qkv + (size_t)(b * SEQ_ + n0) * QKVD_ + h * C_;  // q at cols 0..383
    float* obase = g_attn + (size_t)(b * SEQ_ + n0) * D_ + h * C_;

    const int rr = tid / 12;        // 0..15
    const int dg = tid % 12;        // 0..11 -> cols dg*4..dg*4+3

    for (int r0 = 0; r0 < TB_; r0 += 16) {
        __syncthreads();
        for (int idx = tid; idx < 16 * 48; idx += 192) {
            int r = idx / 48, c = idx % 48;
            eq[r][c] = __expf(qbase[(size_t)(r0 + r) * QKVD_ + c]);
        }
        __syncthreads();
        if (tid < 16) {
            float s = 0.0f;
#pragma unroll
            for (int c = 0; c < 48; c++) s += eq[tid][c];
            srow[tid] = 1.0f / s;
        }
        __syncthreads();
        {
            float4 acc = make_float4(0.f, 0.f, 0.f, 0.f);
#pragma unroll
            for (int c = 0; c < 48; c++) {
                float e = eq[rr][c];
                float4 cv = *(const float4*)&ctxn[c][dg * 4];
                acc.x += e * cv.x; acc.y += e * cv.y; acc.z += e * cv.z; acc.w += e * cv.w;
            }
            float s = srow[rr];
            acc.x *= s; acc.y *= s; acc.z *= s; acc.w *= s;
            *(float4*)&obase[(size_t)(r0 + rr) * D_ + dg * 4] = acc;
        }
    }
}

// ---------------- launch ----------------
extern "C" void kernel_launch(void* const* d_in, const int* in_sizes, int n_in,
                              void* d_out, int out_size)
{
    const float* x     = (const float*)d_in[0];
    const float* Wqkv  = (const float*)d_in[1];
    const float* Wproj = (const float*)d_in[2];
    const float* bproj = (const float*)d_in[3];
    float* out = (float*)d_out;

    float *p_qkv, *p_attn, *p_wtq, *p_wtp;
    cudaGetSymbolAddress((void**)&p_qkv, g_qkv);
    cudaGetSymbolAddress((void**)&p_attn, g_attn);
    cudaGetSymbolAddress((void**)&p_wtq, g_Wtq);
    cudaGetSymbolAddress((void**)&p_wtp, g_Wtp);

    const int smem_bytes = (2 * BM_ * PADS_ + 2 * BN_ * PADS_) * 4;  // 73728
    cudaFuncSetAttribute(gemm_mma, cudaFuncAttributeMaxDynamicSharedMemorySize, smem_bytes);

    // 0) transpose weights to K-major
    transpose_kernel<<<dim3(QKVD_ / 32, D_ / 32), dim3(32, 8)>>>(Wqkv, p_wtq, D_, QKVD_);
    transpose_kernel<<<dim3(D_ / 32, D_ / 32), dim3(32, 8)>>>(Wproj, p_wtp, D_, D_);

    // 1) zero atomic accumulators
    zero_ctx_kernel<<<(B_ * H_ * C_ * C_ + 255) / 256, 256>>>();

    // 2) qkv = x @ W_qkv   [131072 x 384] @ [384 x 1152]
    {
        dim3 grid(QKVD_ / BN_, TOK_ / BM_);
        gemm_mma<<<grid, 256, smem_bytes>>>(x, p_wtq, nullptr, p_qkv, TOK_, QKVD_, D_, 0);
    }

    // 3) context reduction over tokens
    {
        dim3 grid(NSPLIT_, H_, B_);
        dim3 blk(48, 6);
        ctx_kernel<<<grid, blk>>>();
    }

    // 4) q-softmax @ context
    {
        dim3 grid(SEQ_ / TB_, H_, B_);
        attn_kernel<<<grid, 192>>>();
    }

    // 5) out = attn @ W_proj + b_proj   [131072 x 384] @ [384 x 384]
    {
        dim3 grid(D_ / BN_, TOK_ / BM_);
        gemm_mma<<<grid, 256, smem_bytes>>>(p_attn, p_wtp, bproj, out, TOK_, D_, D_, 1);
    }
}

// round 5
// speedup vs baseline: 1.2298x; 1.2298x over previous
#include <cuda_runtime.h>
#include <math.h>
#include <stdint.h>

// Problem constants
#define B_      8
#define SEQ_    16384
#define D_      384
#define QKVD_   1152
#define H_      8
#define C_      48
#define TOK_    (B_ * SEQ_)          // 131072

// ---------------- scratch (static device globals; no allocs allowed) ----------------
__device__ float g_qkv[(size_t)TOK_ * QKVD_];      // 604 MB : x @ W_qkv
__device__ float g_attn[(size_t)TOK_ * D_];        // 201 MB : attention output (tf32-rounded)
__device__ float g_xr[(size_t)TOK_ * D_];          // 201 MB : x rounded to tf32
__device__ float g_ctx[B_ * H_ * C_ * C_];         // unnormalized k^T v context
__device__ float g_sum[B_ * H_ * C_];              // sum of exp(k) over tokens
__device__ float g_Wtq[QKVD_ * D_];                // W_qkv^T, tf32-rounded
__device__ float g_Wtp[D_ * D_];                   // W_proj^T, tf32-rounded

__device__ __forceinline__ float f2tf32(float x) {
    uint32_t y;
    asm("cvt.rna.tf32.f32 %0, %1;" : "=r"(y) : "f"(x));
    return __uint_as_float(y);
}

// ---------------- zero the atomic accumulators (graph replays!) ----------------
__global__ void zero_ctx_kernel() {
    int i = blockIdx.x * 256 + threadIdx.x;
    if (i < B_ * H_ * C_ * C_) g_ctx[i] = 0.0f;
    if (i < B_ * H_ * C_)      g_sum[i] = 0.0f;
}

// ---------------- round x to tf32 (streaming) ----------------
__global__ void round_tf32_kernel(const float4* __restrict__ src, float4* __restrict__ dst, int n4) {
    int i = blockIdx.x * 256 + threadIdx.x;
    if (i < n4) {
        float4 v = src[i];
        v.x = f2tf32(v.x); v.y = f2tf32(v.y); v.z = f2tf32(v.z); v.w = f2tf32(v.w);
        dst[i] = v;
    }
}

// ---------------- weight transpose + tf32 round: src[R][Ccols] -> dst[Ccols][R] ----------------
__global__ void transpose_kernel(const float* __restrict__ src, float* __restrict__ dst,
                                 int R, int Ccols) {
    __shared__ float t[32][33];
    int bx = blockIdx.x * 32, by = blockIdx.y * 32;
    int tx = threadIdx.x, ty = threadIdx.y;
#pragma unroll
    for (int j = 0; j < 32; j += 8)
        t[ty + j][tx] = src[(size_t)(by + ty + j) * Ccols + bx + tx];
    __syncthreads();
#pragma unroll
    for (int j = 0; j < 32; j += 8)
        dst[(size_t)(bx + ty + j) * R + by + tx] = f2tf32(t[tx][ty + j]);
}

// ================= tf32 mma.sync GEMM v3 (no cvt in hot loop; K/N compile-time) =================
// C[M,N] = A[M,K] @ Bt[N,K]^T (+bias). A,Bt pre-rounded to tf32 in memory.
// Block tile 128x128, BK=32, 8 warps (2x4), warp tile 64x32.

#define BM_ 128
#define BN_ 128
#define BK_ 32
#define PADS_ 36                    // floats per smem row

__device__ __forceinline__ uint32_t smem_u32(const void* p) {
    uint32_t a;
    asm("{ .reg .u64 t; cvta.to.shared.u64 t, %1; cvt.u32.u64 %0, t; }" : "=r"(a) : "l"(p));
    return a;
}
__device__ __forceinline__ void cp_async16(uint32_t dst, const void* src) {
    asm volatile("cp.async.cg.shared.global [%0], [%1], 16;" :: "r"(dst), "l"(src));
}
__device__ __forceinline__ void mma_tf32(float* c, const uint32_t* a, const uint32_t* b) {
    asm volatile(
        "mma.sync.aligned.m16n8k8.row.col.f32.tf32.tf32.f32 "
        "{%0,%1,%2,%3}, {%4,%5,%6,%7}, {%8,%9}, {%0,%1,%2,%3};"
        : "+f"(c[0]), "+f"(c[1]), "+f"(c[2]), "+f"(c[3])
        : "r"(a[0]), "r"(a[1]), "r"(a[2]), "r"(a[3]), "r"(b[0]), "r"(b[1]));
}

template <int K, int N, int HAS_BIAS>
__global__ void __launch_bounds__(256, 2)
gemm_mma(const float* __restrict__ A, const float* __restrict__ Bt,
         const float* __restrict__ bias, float* __restrict__ Cm)
{
    extern __shared__ float smem[];
    float* As = smem;                          // 2 * 128 * 36
    float* Bs = smem + 2 * BM_ * PADS_;        // 2 * 128 * 36

    const int tid = threadIdx.x;
    const int wid = tid >> 5;
    const int lane = tid & 31;
    const int m0 = blockIdx.y * BM_;
    const int n0 = blockIdx.x * BN_;
    const int wm = (wid & 1) * 64;       // 2 warps over M
    const int wn = (wid >> 1) * 32;      // 4 warps over N

    const int lr = lane >> 2;   // 0..7
    const int lc = lane & 3;    // 0..3

    const int gr = tid >> 3;          // 0..31
    const int gc = (tid & 7) * 4;     // float offset

    const uint32_t as_base = smem_u32(As);
    const uint32_t bs_base = smem_u32(Bs);

    float acc[4][4][4];
#pragma unroll
    for (int i = 0; i < 4; i++)
#pragma unroll
        for (int j = 0; j < 4; j++)
#pragma unroll
            for (int r = 0; r < 4; r++) acc[i][j][r] = 0.0f;

    constexpr int nch = K / BK_;

    // ---- load chunk 0 ----
    {
#pragma unroll
        for (int i = 0; i < 4; i++) {
            int row = gr + i * 32;
            cp_async16(as_base + (row * PADS_ + gc) * 4, &A[(size_t)(m0 + row) * K + gc]);
            cp_async16(bs_base + (row * PADS_ + gc) * 4, &Bt[(size_t)(n0 + row) * K + gc]);
        }
        asm volatile("cp.async.commit_group;");
    }

#pragma unroll
    for (int c = 0; c < nch; c++) {
        asm volatile("cp.async.wait_group 0;");
        __syncthreads();

        if (c + 1 < nch) {
            const int k0 = (c + 1) * BK_;
            const int buf = (c + 1) & 1;
            const uint32_t ab = as_base + buf * BM_ * PADS_ * 4;
            const uint32_t bb = bs_base + buf * BN_ * PADS_ * 4;
#pragma unroll
            for (int i = 0; i < 4; i++) {
                int row = gr + i * 32;
                cp_async16(ab + (row * PADS_ + gc) * 4, &A[(size_t)(m0 + row) * K + k0 + gc]);
                cp_async16(bb + (row * PADS_ + gc) * 4, &Bt[(size_t)(n0 + row) * K + k0 + gc]);
            }
            asm volatile("cp.async.commit_group;");
        }

        const float* as = As + (c & 1) * BM_ * PADS_;
        const float* bs = Bs + (c & 1) * BN_ * PADS_;

#pragma unroll
        for (int ks = 0; ks < 4; ks++) {
            const int kk = ks * 8 + lc;
            uint32_t afr[4][4];
#pragma unroll
            for (int mi = 0; mi < 4; mi++) {
                int r = wm + mi * 16 + lr;
                afr[mi][0] = __float_as_uint(as[r * PADS_ + kk]);
                afr[mi][1] = __float_as_uint(as[(r + 8) * PADS_ + kk]);
                afr[mi][2] = __float_as_uint(as[r * PADS_ + kk + 4]);
                afr[mi][3] = __float_as_uint(as[(r + 8) * PADS_ + kk + 4]);
            }
            uint32_t bfr[4][2];
#pragma unroll
            for (int nj = 0; nj < 4; nj++) {
                int nn = wn + nj * 8 + lr;
                bfr[nj][0] = __float_as_uint(bs[nn * PADS_ + kk]);
                bfr[nj][1] = __float_as_uint(bs[nn * PADS_ + kk + 4]);
            }
#pragma unroll
            for (int mi = 0; mi < 4; mi++)
#pragma unroll
                for (int nj = 0; nj < 4; nj++)
                    mma_tf32(acc[mi][nj], afr[mi], bfr[nj]);
        }
        __syncthreads();
    }

    // ---- epilogue ----
#pragma unroll
    for (int mi = 0; mi < 4; mi++) {
        const int r0 = m0 + wm + mi * 16 + lr;
#pragma unroll
        for (int nj = 0; nj < 4; nj++) {
            const int col = n0 + wn + nj * 8 + lc * 2;
            float2 b2 = make_float2(0.f, 0.f);
            if (HAS_BIAS) b2 = *(const float2*)&bias[col];
            float2 v0 = make_float2(acc[mi][nj][0] + b2.x, acc[mi][nj][1] + b2.y);
            float2 v1 = make_float2(acc[mi][nj][2] + b2.x, acc[mi][nj][3] + b2.y);
            *(float2*)&Cm[(size_t)r0 * N + col] = v0;
            *(float2*)&Cm[(size_t)(r0 + 8) * N + col] = v1;
        }
    }
}

// ---------------- context: ctx[b,h,c,d] += sum_n exp(k[n,c]) * v[n,d]; sum[c] += sum_n exp(k[n,c]) ----------------
#define NSPLIT_ 128
#define CROWS_  (SEQ_ / NSPLIT_)   // 128

__global__ void __launch_bounds__(288)
ctx_kernel()
{
    const int c = threadIdx.x;                 // 0..47
    const int g = threadIdx.y;                 // 0..5
    const int tid = g * 48 + c;                // 0..287
    const int split = blockIdx.x;
    const int h = blockIdx.y;
    const int b = blockIdx.z;
    const int n0 = split * CROWS_;
    const float* base = g_qkv + (size_t)(b * SEQ_ + n0) * QKVD_ + h * C_;

    __shared__ float ek[32][48];
    __shared__ float vs[32][48];

    float4 acc0 = make_float4(0.f, 0.f, 0.f, 0.f);
    float4 acc1 = make_float4(0.f, 0.f, 0.f, 0.f);
    float ssum = 0.0f;
    const int d0 = g * 8;

    for (int r0 = 0; r0 < CROWS_; r0 += 32) {
        __syncthreads();
        for (int idx = tid; idx < 32 * 48; idx += 288) {
            int r = idx / 48, cc = idx % 48;
            const float* rowp = base + (size_t)(r0 + r) * QKVD_ + cc;
            ek[r][cc] = __expf(rowp[384]);   // k block at cols 384..767
            vs[r][cc] = rowp[768];           // v block at cols 768..1151
        }
        __syncthreads();
#pragma unroll 4
        for (int r = 0; r < 32; r++) {
            float e = ek[r][c];
            if (g == 0) ssum += e;
            float4 v0 = *(const float4*)&vs[r][d0];
            float4 v1 = *(const float4*)&vs[r][d0 + 4];
            acc0.x += e * v0.x; acc0.y += e * v0.y; acc0.z += e * v0.z; acc0.w += e * v0.w;
            acc1.x += e * v1.x; acc1.y += e * v1.y; acc1.z += e * v1.z; acc1.w += e * v1.w;
        }
    }

    float* cp = g_ctx + (((size_t)(b * H_ + h)) * C_ + c) * C_ + d0;
    atomicAdd(&cp[0], acc0.x); atomicAdd(&cp[1], acc0.y);
    atomicAdd(&cp[2], acc0.z); atomicAdd(&cp[3], acc0.w);
    atomicAdd(&cp[4], acc1.x); atomicAdd(&cp[5], acc1.y);
    atomicAdd(&cp[6], acc1.z); atomicAdd(&cp[7], acc1.w);
    if (g == 0) atomicAdd(&g_sum[(b * H_ + h) * C_ + c], ssum);
}

// ---------------- attn v2: 4 rows x 4 cols per thread; output tf32-rounded ----------------
#define TB_ 256   // rows per block, processed in 64-row tiles

__global__ void __launch_bounds__(192)
attn_kernel()
{
    const int tb = blockIdx.x;
    const int h  = blockIdx.y;
    const int b  = blockIdx.z;
    const int tid = threadIdx.x;

    __shared__ float ctxn[48][48];
    __shared__ float eq[64][49];
    __shared__ float srow[64];
    __shared__ float sinv[48];

    if (tid < 48) sinv[tid] = 1.0f / g_sum[(b * H_ + h) * C_ + tid];
    __syncthreads();
    for (int idx = tid; idx < 48 * 48; idx += 192) {
        int c = idx / 48, d = idx % 48;
        ctxn[c][d] = g_ctx[(((size_t)(b * H_ + h)) * C_ + c) * C_ + d] * sinv[c];
    }

    const int n0 = tb * TB_;
    const float* qbase = g_qkv + (size_t)(b * SEQ_ + n0) * QKVD_ + h * C_;  // q at cols 0..383
    float* obase = g_attn + (size_t)(b * SEQ_ + n0) * D_ + h * C_;

    const int rg = tid / 12;        // 0..15 -> rows rg*4 .. rg*4+3
    const int dg = tid % 12;        // 0..11 -> cols dg*4 .. dg*4+3

    for (int t = 0; t < TB_ / 64; t++) {
        const int r0 = t * 64;
        __syncthreads();
        // eq fill: 64 x 48 = 3072 elems, 16 per thread
        for (int idx = tid; idx < 64 * 48; idx += 192) {
            int r = idx / 48, c = idx % 48;
            eq[r][c] = __expf(qbase[(size_t)(r0 + r) * QKVD_ + c]);
        }
        __syncthreads();
        if (tid < 64) {
            float s = 0.0f;
#pragma unroll
            for (int c = 0; c < 48; c++) s += eq[tid][c];
            srow[tid] = 1.0f / s;
        }
        __syncthreads();
        {
            float acc[4][4];
#pragma unroll
            for (int i = 0; i < 4; i++)
#pragma unroll
                for (int j = 0; j < 4; j++) acc[i][j] = 0.0f;
#pragma unroll
            for (int c = 0; c < 48; c++) {
                float4 cv = *(const float4*)&ctxn[c][dg * 4];
                float e0 = eq[rg * 4 + 0][c];
                float e1 = eq[rg * 4 + 1][c];
                float e2 = eq[rg * 4 + 2][c];
                float e3 = eq[rg * 4 + 3][c];
                acc[0][0] += e0 * cv.x; acc[0][1] += e0 * cv.y; acc[0][2] += e0 * cv.z; acc[0][3] += e0 * cv.w;
                acc[1][0] += e1 * cv.x; acc[1][1] += e1 * cv.y; acc[1][2] += e1 * cv.z; acc[1][3] += e1 * cv.w;
                acc[2][0] += e2 * cv.x; acc[2][1] += e2 * cv.y; acc[2][2] += e2 * cv.z; acc[2][3] += e2 * cv.w;
                acc[3][0] += e3 * cv.x; acc[3][1] += e3 * cv.y; acc[3][2] += e3 * cv.z; acc[3][3] += e3 * cv.w;
            }
#pragma unroll
            for (int i = 0; i < 4; i++) {
                const int row = rg * 4 + i;
                float s = srow[row];
                float4 o = make_float4(f2tf32(acc[i][0] * s), f2tf32(acc[i][1] * s),
                                       f2tf32(acc[i][2] * s), f2tf32(acc[i][3] * s));
                *(float4*)&obase[(size_t)(r0 + row) * D_ + dg * 4] = o;
            }
        }
    }
}

// ---------------- launch ----------------
extern "C" void kernel_launch(void* const* d_in, const int* in_sizes, int n_in,
                              void* d_out, int out_size)
{
    const float* x     = (const float*)d_in[0];
    const float* Wqkv  = (const float*)d_in[1];
    const float* Wproj = (const float*)d_in[2];
    const float* bproj = (const float*)d_in[3];
    float* out = (float*)d_out;

    float *p_qkv, *p_attn, *p_xr, *p_wtq, *p_wtp;
    cudaGetSymbolAddress((void**)&p_qkv, g_qkv);
    cudaGetSymbolAddress((void**)&p_attn, g_attn);
    cudaGetSymbolAddress((void**)&p_xr, g_xr);
    cudaGetSymbolAddress((void**)&p_wtq, g_Wtq);
    cudaGetSymbolAddress((void**)&p_wtp, g_Wtp);

    const int smem_bytes = (2 * BM_ * PADS_ + 2 * BN_ * PADS_) * 4;  // 73728
    cudaFuncSetAttribute(gemm_mma<D_, QKVD_, 0>, cudaFuncAttributeMaxDynamicSharedMemorySize, smem_bytes);
    cudaFuncSetAttribute(gemm_mma<D_, D_, 1>, cudaFuncAttributeMaxDynamicSharedMemorySize, smem_bytes);

    // 0) prepasses: round x to tf32; transpose+round weights; zero accumulators
    {
        int n4 = TOK_ * D_ / 4;
        round_tf32_kernel<<<(n4 + 255) / 256, 256>>>((const float4*)x, (float4*)p_xr, n4);
    }
    transpose_kernel<<<dim3(QKVD_ / 32, D_ / 32), dim3(32, 8)>>>(Wqkv, p_wtq, D_, QKVD_);
    transpose_kernel<<<dim3(D_ / 32, D_ / 32), dim3(32, 8)>>>(Wproj, p_wtp, D_, D_);
    zero_ctx_kernel<<<(B_ * H_ * C_ * C_ + 255) / 256, 256>>>();

    // 1) qkv = x @ W_qkv   [131072 x 384] @ [384 x 1152]
    {
        dim3 grid(QKVD_ / BN_, TOK_ / BM_);
        gemm_mma<D_, QKVD_, 0><<<grid, 256, smem_bytes>>>(p_xr, p_wtq, nullptr, p_qkv);
    }

    // 2) context reduction over tokens
    {
        dim3 grid(NSPLIT_, H_, B_);
        dim3 blk(48, 6);
        ctx_kernel<<<grid, blk>>>();
    }

    // 3) q-softmax @ context (writes tf32-rounded attn)
    {
        dim3 grid(SEQ_ / TB_, H_, B_);
        attn_kernel<<<grid, 192>>>();
    }

    // 4) out = attn @ W_proj + b_proj   [131072 x 384] @ [384 x 384]
    {
        dim3 grid(D_ / BN_, TOK_ / BM_);
        gemm_mma<D_, D_, 1><<<grid, 256, smem_bytes>>>(p_attn, p_wtp, bproj, out);
    }
}

// round 6
// speedup vs baseline: 1.3753x; 1.1183x over previous
#include <cuda_runtime.h>
#include <math.h>
#include <stdint.h>

// Problem constants
#define B_      8
#define SEQ_    16384
#define D_      384
#define H_      8
#define C_      48
#define TOK_    (B_ * SEQ_)          // 131072

// ---------------- scratch (static device globals; no allocs allowed) ----------------
__device__ float g_q[(size_t)TOK_ * D_];           // 201 MB : q = x @ Wq
__device__ float g_attn[(size_t)TOK_ * D_];        // 201 MB : attention output (tf32-rounded)
__device__ float g_xr[(size_t)TOK_ * D_];          // 201 MB : x rounded to tf32
__device__ float g_ctx[B_ * H_ * C_ * C_];         // unnormalized k^T v context
__device__ float g_sum[B_ * H_ * C_];              // sum of exp(k) over tokens
__device__ float g_Wtq[3 * D_ * D_];               // W_qkv^T, tf32-rounded  [1152][384]
__device__ float g_Wtp[D_ * D_];                   // W_proj^T, tf32-rounded

__device__ __forceinline__ float f2tf32(float x) {
    uint32_t y;
    asm("cvt.rna.tf32.f32 %0, %1;" : "=r"(y) : "f"(x));
    return __uint_as_float(y);
}
__device__ __forceinline__ uint32_t smem_u32(const void* p) {
    uint32_t a;
    asm("{ .reg .u64 t; cvta.to.shared.u64 t, %1; cvt.u32.u64 %0, t; }" : "=r"(a) : "l"(p));
    return a;
}
__device__ __forceinline__ void cp_async16(uint32_t dst, const void* src) {
    asm volatile("cp.async.cg.shared.global [%0], [%1], 16;" :: "r"(dst), "l"(src));
}
__device__ __forceinline__ void mma_tf32(float* c, const uint32_t* a, const uint32_t* b) {
    asm volatile(
        "mma.sync.aligned.m16n8k8.row.col.f32.tf32.tf32.f32 "
        "{%0,%1,%2,%3}, {%4,%5,%6,%7}, {%8,%9}, {%0,%1,%2,%3};"
        : "+f"(c[0]), "+f"(c[1]), "+f"(c[2]), "+f"(c[3])
        : "r"(a[0]), "r"(a[1]), "r"(a[2]), "r"(a[3]), "r"(b[0]), "r"(b[1]));
}

// ---------------- zero the atomic accumulators (graph replays!) ----------------
__global__ void zero_ctx_kernel() {
    int i = blockIdx.x * 256 + threadIdx.x;
    if (i < B_ * H_ * C_ * C_) g_ctx[i] = 0.0f;
    if (i < B_ * H_ * C_)      g_sum[i] = 0.0f;
}

// ---------------- round x to tf32 (streaming) ----------------
__global__ void round_tf32_kernel(const float4* __restrict__ src, float4* __restrict__ dst, int n4) {
    int i = blockIdx.x * 256 + threadIdx.x;
    if (i < n4) {
        float4 v = src[i];
        v.x = f2tf32(v.x); v.y = f2tf32(v.y); v.z = f2tf32(v.z); v.w = f2tf32(v.w);
        dst[i] = v;
    }
}

// ---------------- weight transpose + tf32 round: src[R][Ccols] -> dst[Ccols][R] ----------------
__global__ void transpose_kernel(const float* __restrict__ src, float* __restrict__ dst,
                                 int R, int Ccols) {
    __shared__ float t[32][33];
    int bx = blockIdx.x * 32, by = blockIdx.y * 32;
    int tx = threadIdx.x, ty = threadIdx.y;
#pragma unroll
    for (int j = 0; j < 32; j += 8)
        t[ty + j][tx] = src[(size_t)(by + ty + j) * Ccols + bx + tx];
    __syncthreads();
#pragma unroll
    for (int j = 0; j < 32; j += 8)
        dst[(size_t)(bx + ty + j) * R + by + tx] = f2tf32(t[tx][ty + j]);
}

// ================= tf32 mma.sync GEMM (block 128x128, BK=32, 8 warps 2x4, warp 64x32) =================
#define BM_ 128
#define BN_ 128
#define BK_ 32
#define PADS_ 36

template <int K, int N, int HAS_BIAS>
__global__ void __launch_bounds__(256, 2)
gemm_mma(const float* __restrict__ A, const float* __restrict__ Bt,
         const float* __restrict__ bias, float* __restrict__ Cm)
{
    extern __shared__ float smem[];
    float* As = smem;
    float* Bs = smem + 2 * BM_ * PADS_;

    const int tid = threadIdx.x;
    const int wid = tid >> 5;
    const int lane = tid & 31;
    const int m0 = blockIdx.y * BM_;
    const int n0 = blockIdx.x * BN_;
    const int wm = (wid & 1) * 64;
    const int wn = (wid >> 1) * 32;
    const int lr = lane >> 2;
    const int lc = lane & 3;
    const int gr = tid >> 3;
    const int gc = (tid & 7) * 4;

    const uint32_t as_base = smem_u32(As);
    const uint32_t bs_base = smem_u32(Bs);

    float acc[4][4][4];
#pragma unroll
    for (int i = 0; i < 4; i++)
#pragma unroll
        for (int j = 0; j < 4; j++)
#pragma unroll
            for (int r = 0; r < 4; r++) acc[i][j][r] = 0.0f;

    constexpr int nch = K / BK_;

    {
#pragma unroll
        for (int i = 0; i < 4; i++) {
            int row = gr + i * 32;
            cp_async16(as_base + (row * PADS_ + gc) * 4, &A[(size_t)(m0 + row) * K + gc]);
            cp_async16(bs_base + (row * PADS_ + gc) * 4, &Bt[(size_t)(n0 + row) * K + gc]);
        }
        asm volatile("cp.async.commit_group;");
    }

#pragma unroll
    for (int c = 0; c < nch; c++) {
        asm volatile("cp.async.wait_group 0;");
        __syncthreads();

        if (c + 1 < nch) {
            const int k0 = (c + 1) * BK_;
            const int buf = (c + 1) & 1;
            const uint32_t ab = as_base + buf * BM_ * PADS_ * 4;
            const uint32_t bb = bs_base + buf * BN_ * PADS_ * 4;
#pragma unroll
            for (int i = 0; i < 4; i++) {
                int row = gr + i * 32;
                cp_async16(ab + (row * PADS_ + gc) * 4, &A[(size_t)(m0 + row) * K + k0 + gc]);
                cp_async16(bb + (row * PADS_ + gc) * 4, &Bt[(size_t)(n0 + row) * K + k0 + gc]);
            }
            asm volatile("cp.async.commit_group;");
        }

        const float* as = As + (c & 1) * BM_ * PADS_;
        const float* bs = Bs + (c & 1) * BN_ * PADS_;

#pragma unroll
        for (int ks = 0; ks < 4; ks++) {
            const int kk = ks * 8 + lc;
            uint32_t afr[4][4];
#pragma unroll
            for (int mi = 0; mi < 4; mi++) {
                int r = wm + mi * 16 + lr;
                afr[mi][0] = __float_as_uint(as[r * PADS_ + kk]);
                afr[mi][1] = __float_as_uint(as[(r + 8) * PADS_ + kk]);
                afr[mi][2] = __float_as_uint(as[r * PADS_ + kk + 4]);
                afr[mi][3] = __float_as_uint(as[(r + 8) * PADS_ + kk + 4]);
            }
            uint32_t bfr[4][2];
#pragma unroll
            for (int nj = 0; nj < 4; nj++) {
                int nn = wn + nj * 8 + lr;
                bfr[nj][0] = __float_as_uint(bs[nn * PADS_ + kk]);
                bfr[nj][1] = __float_as_uint(bs[nn * PADS_ + kk + 4]);
            }
#pragma unroll
            for (int mi = 0; mi < 4; mi++)
#pragma unroll
                for (int nj = 0; nj < 4; nj++)
                    mma_tf32(acc[mi][nj], afr[mi], bfr[nj]);
        }
        __syncthreads();
    }

#pragma unroll
    for (int mi = 0; mi < 4; mi++) {
        const int r0 = m0 + wm + mi * 16 + lr;
#pragma unroll
        for (int nj = 0; nj < 4; nj++) {
            const int col = n0 + wn + nj * 8 + lc * 2;
            float2 b2 = make_float2(0.f, 0.f);
            if (HAS_BIAS) b2 = *(const float2*)&bias[col];
            float2 v0 = make_float2(acc[mi][nj][0] + b2.x, acc[mi][nj][1] + b2.y);
            float2 v1 = make_float2(acc[mi][nj][2] + b2.x, acc[mi][nj][3] + b2.y);
            *(float2*)&Cm[(size_t)r0 * N + col] = v0;
            *(float2*)&Cm[(size_t)(r0 + 8) * N + col] = v1;
        }
    }
}

// ================= fused kv-GEMM + ctx kernel =================
// Grid (4 colgroups, 256 supersets). Each CTA: 4 rowblocks of 128 tokens.
// Per rowblock: compute k[128x96], v[128x96] (heads 2cg, 2cg+1), exp(k) -> smem,
// ctx[2][48][48] += e^T v via tensor cores (accumulated in regs), atomics at end.
#define KVN_ 192
#define ST_  132   // eT/vT row stride in floats (132 % 32 == 4 -> conflict-free frags)
#define KV_SMEM_FLOATS (2 * 96 * ST_)     // 25344 floats = 101376 B (>= mainloop's 23040)

__global__ void __launch_bounds__(256, 1)
kv_ctx_kernel()
{
    extern __shared__ float smem[];
    float* As = smem;                       // [2][128][36]
    float* Bs = smem + 2 * BM_ * PADS_;     // [2][192][36]
    float* eT = smem;                       // [96][ST_]   (epilogue view)
    float* vT = smem + 96 * ST_;            // [96][ST_]

    const int tid = threadIdx.x;
    const int wid = tid >> 5;
    const int lane = tid & 31;
    const int cg = blockIdx.x;              // 0..3 -> heads 2cg, 2cg+1
    const int ss = blockIdx.y;              // 0..255 (512-token superset)
    const int lr = lane >> 2;
    const int lc = lane & 3;
    const int wm = (wid & 1) * 64;          // 2 warps over M
    const int wn = (wid >> 1) * 48;         // 4 warps over N=192
    const int gr = tid >> 3;
    const int gc = (tid & 7) * 4;

    const uint32_t as_base = smem_u32(As);
    const uint32_t bs_base = smem_u32(Bs);

    const float* Wk = g_Wtq + (size_t)(D_ + cg * 96) * D_;       // k-chan weights
    const float* Wv = g_Wtq + (size_t)(2 * D_ + cg * 96) * D_;   // v-chan weights

    const int batch = ss / 32;

    float ctxa[5][4];
#pragma unroll
    for (int i = 0; i < 5; i++)
#pragma unroll
        for (int r = 0; r < 4; r++) ctxa[i][r] = 0.0f;
    float ssum = 0.0f;

    for (int rb = 0; rb < 4; rb++) {
        const size_t tok0 = ((size_t)ss * 4 + rb) * 128;
        const float* A = g_xr + tok0 * D_;

        float acc[4][6][4];
#pragma unroll
        for (int i = 0; i < 4; i++)
#pragma unroll
            for (int j = 0; j < 6; j++)
#pragma unroll
                for (int r = 0; r < 4; r++) acc[i][j][r] = 0.0f;

        // prefetch chunk 0
        {
#pragma unroll
            for (int i = 0; i < 4; i++) {
                int row = gr + i * 32;
                cp_async16(as_base + (row * PADS_ + gc) * 4, &A[(size_t)row * D_ + gc]);
            }
#pragma unroll
            for (int i = 0; i < 6; i++) {
                int row = gr + i * 32;
                const float* src = (row < 96) ? &Wk[(size_t)row * D_ + gc]
                                              : &Wv[(size_t)(row - 96) * D_ + gc];
                cp_async16(bs_base + (row * PADS_ + gc) * 4, src);
            }
            asm volatile("cp.async.commit_group;");
        }

#pragma unroll
        for (int c = 0; c < D_ / BK_; c++) {
            asm volatile("cp.async.wait_group 0;");
            __syncthreads();

            if (c + 1 < D_ / BK_) {
                const int k0 = (c + 1) * BK_;
                const int buf = (c + 1) & 1;
                const uint32_t ab = as_base + buf * BM_ * PADS_ * 4;
                const uint32_t bb = bs_base + buf * KVN_ * PADS_ * 4;
#pragma unroll
                for (int i = 0; i < 4; i++) {
                    int row = gr + i * 32;
                    cp_async16(ab + (row * PADS_ + gc) * 4, &A[(size_t)row * D_ + k0 + gc]);
                }
#pragma unroll
                for (int i = 0; i < 6; i++) {
                    int row = gr + i * 32;
                    const float* src = (row < 96) ? &Wk[(size_t)row * D_ + k0 + gc]
                                                  : &Wv[(size_t)(row - 96) * D_ + k0 + gc];
                    cp_async16(bb + (row * PADS_ + gc) * 4, src);
                }
                asm volatile("cp.async.commit_group;");
            }

            const float* as = As + (c & 1) * BM_ * PADS_;
            const float* bs = Bs + (c & 1) * KVN_ * PADS_;

#pragma unroll
            for (int ks = 0; ks < 4; ks++) {
                const int kk = ks * 8 + lc;
                uint32_t afr[4][4];
#pragma unroll
                for (int mi = 0; mi < 4; mi++) {
                    int r = wm + mi * 16 + lr;
                    afr[mi][0] = __float_as_uint(as[r * PADS_ + kk]);
                    afr[mi][1] = __float_as_uint(as[(r + 8) * PADS_ + kk]);
                    afr[mi][2] = __float_as_uint(as[r * PADS_ + kk + 4]);
                    afr[mi][3] = __float_as_uint(as[(r + 8) * PADS_ + kk + 4]);
                }
                uint32_t bfr[6][2];
#pragma unroll
                for (int nj = 0; nj < 6; nj++) {
                    int nn = wn + nj * 8 + lr;
                    bfr[nj][0] = __float_as_uint(bs[nn * PADS_ + kk]);
                    bfr[nj][1] = __float_as_uint(bs[nn * PADS_ + kk + 4]);
                }
#pragma unroll
                for (int mi = 0; mi < 4; mi++)
#pragma unroll
                    for (int nj = 0; nj < 6; nj++)
                        mma_tf32(acc[mi][nj], afr[mi], bfr[nj]);
            }
            __syncthreads();
        }

        // ---- epilogue: store exp(k)^T and v^T into smem (tf32-rounded) ----
        // warp cols wn..wn+47: wid 0-3 -> k chans 0..95 ; wid 4-7 -> v chans 0..95
#pragma unroll
        for (int mi = 0; mi < 4; mi++) {
#pragma unroll
            for (int nj = 0; nj < 6; nj++) {
#pragma unroll
                for (int r = 0; r < 4; r++) {
                    int ch = wn + nj * 8 + lc * 2 + (r & 1);
                    int tl = wm + mi * 16 + lr + ((r >> 1) ? 8 : 0);
                    if (wid < 4) {
                        eT[ch * ST_ + tl] = f2tf32(__expf(acc[mi][nj][r]));
                    } else {
                        vT[(ch - 96) * ST_ + tl] = f2tf32(acc[mi][nj][r]);
                    }
                }
            }
        }
        __syncthreads();

        // ---- ctx += e^T v via tensor cores: 36 m16n8 tiles (2 heads x 3m x 6n), k=128 ----
#pragma unroll
        for (int i = 0; i < 5; i++) {
            int t = wid + 8 * i;
            if (t < 36) {
                int head = t / 18, rem = t % 18;
                int mi = rem / 6, nj = rem % 6;
                const float* ea = eT + (head * 48 + mi * 16) * ST_;
                const float* vb = vT + (head * 48 + nj * 8) * ST_;
#pragma unroll
                for (int ks = 0; ks < 16; ks++) {
                    const int kk = ks * 8 + lc;
                    uint32_t a[4], b[2];
                    a[0] = __float_as_uint(ea[lr * ST_ + kk]);
                    a[1] = __float_as_uint(ea[(lr + 8) * ST_ + kk]);
                    a[2] = __float_as_uint(ea[lr * ST_ + kk + 4]);
                    a[3] = __float_as_uint(ea[(lr + 8) * ST_ + kk + 4]);
                    b[0] = __float_as_uint(vb[lr * ST_ + kk]);
                    b[1] = __float_as_uint(vb[lr * ST_ + kk + 4]);
                    mma_tf32(ctxa[i], a, b);
                }
            }
        }

        // ---- per-channel exp-sum (threads 0..95) ----
        if (tid < 96) {
            const float* row = eT + tid * ST_;
            float s = 0.0f;
#pragma unroll
            for (int j = 0; j < 32; j++) {
                float4 v = *(const float4*)&row[j * 4];
                s += (v.x + v.y) + (v.z + v.w);
            }
            ssum += s;
        }
        __syncthreads();   // protect eT/vT before next rowblock's cp.async
    }

    // ---- atomics ----
#pragma unroll
    for (int i = 0; i < 5; i++) {
        int t = wid + 8 * i;
        if (t < 36) {
            int head = t / 18, rem = t % 18;
            int mi = rem / 6, nj = rem % 6;
            int bh = (batch * H_ + cg * 2 + head);
#pragma unroll
            for (int r = 0; r < 4; r++) {
                int c = mi * 16 + lr + ((r >> 1) ? 8 : 0);
                int d = nj * 8 + lc * 2 + (r & 1);
                atomicAdd(&g_ctx[((size_t)bh * C_ + c) * C_ + d], ctxa[i][r]);
            }
        }
    }
    if (tid < 96) {
        int head = tid / 48;
        atomicAdd(&g_sum[(batch * H_ + cg * 2 + head) * C_ + tid % 48], ssum);
    }
}

// ---------------- attn: out[t, h*48+d] = softmax_c(q[t,h,:]) @ ctxn ----------------
#define TB_ 256

__global__ void __launch_bounds__(192)
attn_kernel()
{
    const int tb = blockIdx.x;
    const int h  = blockIdx.y;
    const int b  = blockIdx.z;
    const int tid = threadIdx.x;

    __shared__ float ctxn[48][48];
    __shared__ float eq[64][49];
    __shared__ float srow[64];
    __shared__ float sinv[48];

    if (tid < 48) sinv[tid] = 1.0f / g_sum[(b * H_ + h) * C_ + tid];
    __syncthreads();
    for (int idx = tid; idx < 48 * 48; idx += 192) {
        int c = idx / 48, d = idx % 48;
        ctxn[c][d] = g_ctx[(((size_t)(b * H_ + h)) * C_ + c) * C_ + d] * sinv[c];
    }

    const int n0 = tb * TB_;
    const float* qbase = g_q + (size_t)(b * SEQ_ + n0) * D_ + h * C_;
    float* obase = g_attn + (size_t)(b * SEQ_ + n0) * D_ + h * C_;

    const int rg = tid / 12;
    const int dg = tid % 12;

    for (int t = 0; t < TB_ / 64; t++) {
        const int r0 = t * 64;
        __syncthreads();
        for (int idx = tid; idx < 64 * 48; idx += 192) {
            int r = idx / 48, c = idx % 48;
            eq[r][c] = __expf(qbase[(size_t)(r0 + r) * D_ + c]);
        }
        __syncthreads();
        if (tid < 64) {
            float s = 0.0f;
#pragma unroll
            for (int c = 0; c < 48; c++) s += eq[tid][c];
            srow[tid] = 1.0f / s;
        }
        __syncthreads();
        {
            float acc[4][4];
#pragma unroll
            for (int i = 0; i < 4; i++)
#pragma unroll
                for (int j = 0; j < 4; j++) acc[i][j] = 0.0f;
#pragma unroll
            for (int c = 0; c < 48; c++) {
                float4 cv = *(const float4*)&ctxn[c][dg * 4];
                float e0 = eq[rg * 4 + 0][c];
                float e1 = eq[rg * 4 + 1][c];
                float e2 = eq[rg * 4 + 2][c];
                float e3 = eq[rg * 4 + 3][c];
                acc[0][0] += e0 * cv.x; acc[0][1] += e0 * cv.y; acc[0][2] += e0 * cv.z; acc[0][3] += e0 * cv.w;
                acc[1][0] += e1 * cv.x; acc[1][1] += e1 * cv.y; acc[1][2] += e1 * cv.z; acc[1][3] += e1 * cv.w;
                acc[2][0] += e2 * cv.x; acc[2][1] += e2 * cv.y; acc[2][2] += e2 * cv.z; acc[2][3] += e2 * cv.w;
                acc[3][0] += e3 * cv.x; acc[3][1] += e3 * cv.y; acc[3][2] += e3 * cv.z; acc[3][3] += e3 * cv.w;
            }
#pragma unroll
            for (int i = 0; i < 4; i++) {
                const int row = rg * 4 + i;
                float s = srow[row];
                float4 o = make_float4(f2tf32(acc[i][0] * s), f2tf32(acc[i][1] * s),
                                       f2tf32(acc[i][2] * s), f2tf32(acc[i][3] * s));
                *(float4*)&obase[(size_t)(r0 + row) * D_ + dg * 4] = o;
            }
        }
    }
}

// ---------------- launch ----------------
extern "C" void kernel_launch(void* const* d_in, const int* in_sizes, int n_in,
                              void* d_out, int out_size)
{
    const float* x     = (const float*)d_in[0];
    const float* Wqkv  = (const float*)d_in[1];
    const float* Wproj = (const float*)d_in[2];
    const float* bproj = (const float*)d_in[3];
    float* out = (float*)d_out;

    float *p_q, *p_attn, *p_xr, *p_wtq, *p_wtp;
    cudaGetSymbolAddress((void**)&p_q, g_q);
    cudaGetSymbolAddress((void**)&p_attn, g_attn);
    cudaGetSymbolAddress((void**)&p_xr, g_xr);
    cudaGetSymbolAddress((void**)&p_wtq, g_Wtq);
    cudaGetSymbolAddress((void**)&p_wtp, g_Wtp);

    const int gemm_smem = (2 * BM_ * PADS_ + 2 * BN_ * PADS_) * 4;   // 73728
    const int kv_smem = KV_SMEM_FLOATS * 4;                          // 101376
    cudaFuncSetAttribute(gemm_mma<D_, D_, 0>, cudaFuncAttributeMaxDynamicSharedMemorySize, gemm_smem);
    cudaFuncSetAttribute(gemm_mma<D_, D_, 1>, cudaFuncAttributeMaxDynamicSharedMemorySize, gemm_smem);
    cudaFuncSetAttribute(kv_ctx_kernel, cudaFuncAttributeMaxDynamicSharedMemorySize, kv_smem);

    // 0) prepasses
    {
        int n4 = TOK_ * D_ / 4;
        round_tf32_kernel<<<(n4 + 255) / 256, 256>>>((const float4*)x, (float4*)p_xr, n4);
    }
    transpose_kernel<<<dim3(3 * D_ / 32, D_ / 32), dim3(32, 8)>>>(Wqkv, p_wtq, D_, 3 * D_);
    transpose_kernel<<<dim3(D_ / 32, D_ / 32), dim3(32, 8)>>>(Wproj, p_wtp, D_, D_);
    zero_ctx_kernel<<<(B_ * H_ * C_ * C_ + 255) / 256, 256>>>();

    // 1) q = x @ Wq   [131072 x 384] @ [384 x 384]
    {
        dim3 grid(D_ / BN_, TOK_ / BM_);
        gemm_mma<D_, D_, 0><<<grid, 256, gemm_smem>>>(p_xr, p_wtq, nullptr, p_q);
    }

    // 2) fused kv-GEMM + context accumulation
    {
        dim3 grid(4, 256);
        kv_ctx_kernel<<<grid, 256, kv_smem>>>();
    }

    // 3) q-softmax @ context (writes tf32-rounded attn)
    {
        dim3 grid(SEQ_ / TB_, H_, B_);
        attn_kernel<<<grid, 192>>>();
    }

    // 4) out = attn @ W_proj + b_proj
    {
        dim3 grid(D_ / BN_, TOK_ / BM_);
        gemm_mma<D_, D_, 1><<<grid, 256, gemm_smem>>>(p_attn, p_wtp, bproj, out);
    }
}